// round 13
// baseline (speedup 1.0000x reference)
#include <cuda_runtime.h>
#include <cuda_fp16.h>
#include <cstdint>

// Problem constants
#define NN   50000
#define HID  128
#define NC   8
#define NS   5
#define NK   16
#define TM   64                          // nodes per tile
#define NT2  ((NN + TM - 1) / TM)        // 782 tiles
#define GRID1 296                        // persistent CTAs, 2 per SM

// probs scratch: fp32 (self-pred reads) + fp16 mirror (neighbor gathers).
__device__ float   g_probs[NN * NC];       // 1.6MB
__device__ __half2 g_probs_h[NN * 4];      // 800KB

// ---------------------------------------------------------------------------
// SMEM layout (bytes). W1 split-fp16 images (hi+lo) stored [k][n] (.trans-fed);
// A single fp16 image [m][k] (no residual: 2-pass scheme D = Ah*(Bh+Bl)).
// Rows are 256B = 16 chunks of 16B; chunk index XOR-swizzled with (row & 7)
// for conflict-free ldmatrix.
// ---------------------------------------------------------------------------
#define OFF_BH   0                        // 128x128 fp16 = 32768
#define OFF_BL   32768                    // 32768
#define OFF_AH   65536                    // 64x128 fp16 = 16384
#define OFF_W2   81920                    // 128x8 f32 = 4096
#define OFF_B1   86016                    // 128 f32
#define OFF_B2   86528                    // 8 f32 (+pad)
#define OFF_PART 86656                    // 64x8 f32 = 2048
#define SMEM_TOTAL 88704

__device__ __forceinline__ uint32_t smem_u32(const void* p) {
    uint32_t a;
    asm("{ .reg .u64 t; cvta.to.shared.u64 t, %1; cvt.u32.u64 %0, t; }" : "=r"(a) : "l"(p));
    return a;
}
__device__ __forceinline__ void ldsm4(uint32_t& r0, uint32_t& r1, uint32_t& r2, uint32_t& r3,
                                      uint32_t addr) {
    asm volatile("ldmatrix.sync.aligned.m8n8.x4.shared.b16 {%0,%1,%2,%3}, [%4];"
                 : "=r"(r0), "=r"(r1), "=r"(r2), "=r"(r3) : "r"(addr));
}
__device__ __forceinline__ void ldsm4t(uint32_t& r0, uint32_t& r1, uint32_t& r2, uint32_t& r3,
                                       uint32_t addr) {
    asm volatile("ldmatrix.sync.aligned.m8n8.x4.trans.shared.b16 {%0,%1,%2,%3}, [%4];"
                 : "=r"(r0), "=r"(r1), "=r"(r2), "=r"(r3) : "r"(addr));
}
__device__ __forceinline__ void mma_f16(float* d,
                                        uint32_t a0, uint32_t a1, uint32_t a2, uint32_t a3,
                                        uint32_t b0, uint32_t b1) {
    asm("mma.sync.aligned.m16n8k16.row.col.f32.f16.f16.f32 "
        "{%0,%1,%2,%3}, {%4,%5,%6,%7}, {%8,%9}, {%0,%1,%2,%3};"
        : "+f"(d[0]), "+f"(d[1]), "+f"(d[2]), "+f"(d[3])
        : "r"(a0), "r"(a1), "r"(a2), "r"(a3), "r"(b0), "r"(b1));
}
__device__ __forceinline__ uint32_t pack2h(float x, float y) {
    __half hx = __float2half_rn(x), hy = __float2half_rn(y);
    return (uint32_t)__half_as_ushort(hx) | ((uint32_t)__half_as_ushort(hy) << 16);
}
// Split (x,y) into packed-fp16 hi pair and lo (residual) pair.
__device__ __forceinline__ void split2h(float x, float y, uint32_t& hi, uint32_t& lo) {
    __half hx = __float2half_rn(x), hy = __float2half_rn(y);
    __half lx = __float2half_rn(x - __half2float(hx));
    __half ly = __float2half_rn(y - __half2float(hy));
    hi = (uint32_t)__half_as_ushort(hx) | ((uint32_t)__half_as_ushort(hy) << 16);
    lo = (uint32_t)__half_as_ushort(lx) | ((uint32_t)__half_as_ushort(ly) << 16);
}

// ---------------------------------------------------------------------------
// Stage 1: probs = softmax(relu(feats@W1+b1)@W2+b2) via HMMA fp16, 2-pass
// split on the weight side only: D = Ah*Bh + Ah*Bl (error ~2^-12, ~1e-4 norm).
// 8 warps: mi = w&3 (16 M-rows each), ni = w>>2 (64 N-cols each).
// A fragments are loaded ONCE per k-step and reused for both B passes.
// Layer 2 reuses the layer-1 D fragments directly as mma A fragments.
// Epilogue stores probs twice: fp32 (self-pred) + half2 (gather mirror).
// ---------------------------------------------------------------------------
__global__ __launch_bounds__(256, 2)
void mlp_tc_kernel(const float* __restrict__ feats,
                   const float* __restrict__ W1,
                   const float* __restrict__ b1,
                   const float* __restrict__ W2,
                   const float* __restrict__ b2)
{
    extern __shared__ char smem[];
    const uint32_t sb = smem_u32(smem);
    const int tid  = threadIdx.x;
    const int lane = tid & 31;
    const int w    = tid >> 5;
    const int mi   = w & 3;
    const int ni   = w >> 2;

    float* W2s  = (float*)(smem + OFF_W2);
    float* b1s  = (float*)(smem + OFF_B1);
    float* b2s  = (float*)(smem + OFF_B2);
    float* part = (float*)(smem + OFF_PART);

    // ---- prologue: W1 -> Bh/Bl ([k][n] fp16 split, swizzled), W2, biases ----
    {
        const float4* w1v = (const float4*)W1;
        #pragma unroll
        for (int r = 0; r < 16; r++) {
            int idx = tid + 256 * r;           // 0..4095
            int k = idx >> 5, q = idx & 31;    // row k, float4 q
            float4 v = w1v[idx];
            uint32_t hp0, lp0, hp1, lp1;
            split2h(v.x, v.y, hp0, lp0);
            split2h(v.z, v.w, hp1, lp1);
            uint32_t off = (uint32_t)k * 256 + ((uint32_t)((q >> 1) ^ (k & 7)) << 4)
                         + ((uint32_t)(q & 1) << 3);
            *(uint2*)(smem + OFF_BH + off) = make_uint2(hp0, hp1);
            *(uint2*)(smem + OFF_BL + off) = make_uint2(lp0, lp1);
        }
        ((float4*)W2s)[tid] = ((const float4*)W2)[tid];   // 1024 floats
        if (tid < HID) b1s[tid] = b1[tid];
        if (tid < NC)  b2s[tid] = b2[tid];
    }
    __syncthreads();

    // ---- per-warp constants ----
    const int cc = lane >> 2;            // class (mma2 n) / D row group
    const int kp = (lane & 3) * 2;       // col-pair base within 8-wide tiles
    const int g  = lane >> 3;            // ldmatrix address group
    const int lr = lane & 7;
    const int g1 = g & 1, g2 = g >> 1;

    // A ldmatrix lane constants
    const int arow = mi * 16 + lr + g1 * 8;
    const uint32_t a_rowoff = (uint32_t)arow * 256;
    const int asw = arow & 7;
    // B ldmatrix lane constants per ntile-pair pp (k-row swizzle index = lr)
    uint32_t bconst[4];
    #pragma unroll
    for (int pp = 0; pp < 4; pp++)
        bconst[pp] = (uint32_t)(lr + g1 * 8) * 256
                   + ((uint32_t)((ni * 8 + 2 * pp + g2) ^ lr) << 4);

    // W2 fragments (hi/lo fp16) for layer-2 mma, precomputed once
    uint32_t w2h[4][2], w2l[4][2];
    #pragma unroll
    for (int s2 = 0; s2 < 4; s2++) {
        int j0 = ni * 64 + s2 * 16 + kp;
        split2h(W2s[j0 * 8 + cc],       W2s[(j0 + 1) * 8 + cc], w2h[s2][0], w2l[s2][0]);
        split2h(W2s[(j0 + 8) * 8 + cc], W2s[(j0 + 9) * 8 + cc], w2h[s2][1], w2l[s2][1]);
    }

    // ---- persistent tile loop ----
    for (int tile = blockIdx.x; tile < NT2; tile += GRID1) {
        const int node0 = tile * TM;

        // A prep: fp32 -> fp16 (no residual), swizzled [m][k]
        {
            const float4* fv = (const float4*)feats;
            #pragma unroll
            for (int r = 0; r < 8; r++) {
                int idx = tid + 256 * r;          // 0..2047
                int m = idx >> 5, q = idx & 31;
                int gn = node0 + m;
                float4 v = (gn < NN) ? fv[(size_t)gn * 32 + q]
                                     : make_float4(0.f, 0.f, 0.f, 0.f);
                uint32_t off = (uint32_t)m * 256 + ((uint32_t)((q >> 1) ^ (m & 7)) << 4)
                             + ((uint32_t)(q & 1) << 3);
                *(uint2*)(smem + OFF_AH + off) =
                    make_uint2(pack2h(v.x, v.y), pack2h(v.z, v.w));
            }
        }
        __syncthreads();

        // ---- layer 1: 2-pass (Bh, Bl) with shared A fragments ----
        float d[8][4];
        #pragma unroll
        for (int t = 0; t < 8; t++) { d[t][0] = d[t][1] = d[t][2] = d[t][3] = 0.f; }

        const uint32_t abase  = sb + OFF_AH + a_rowoff;
        const uint32_t bhbase = sb + OFF_BH;
        const uint32_t blbase = sb + OFF_BL;
        #pragma unroll
        for (int s = 0; s < 8; s++) {
            uint32_t a0, a1, a2, a3;
            ldsm4(a0, a1, a2, a3, abase + ((uint32_t)((2 * s + g2) ^ asw) << 4));
            uint32_t bh[8][2], bl[8][2];
            ldsm4t(bh[0][0], bh[0][1], bh[1][0], bh[1][1], bhbase + bconst[0] + (s << 12));
            ldsm4t(bh[2][0], bh[2][1], bh[3][0], bh[3][1], bhbase + bconst[1] + (s << 12));
            ldsm4t(bh[4][0], bh[4][1], bh[5][0], bh[5][1], bhbase + bconst[2] + (s << 12));
            ldsm4t(bh[6][0], bh[6][1], bh[7][0], bh[7][1], bhbase + bconst[3] + (s << 12));
            ldsm4t(bl[0][0], bl[0][1], bl[1][0], bl[1][1], blbase + bconst[0] + (s << 12));
            ldsm4t(bl[2][0], bl[2][1], bl[3][0], bl[3][1], blbase + bconst[1] + (s << 12));
            ldsm4t(bl[4][0], bl[4][1], bl[5][0], bl[5][1], blbase + bconst[2] + (s << 12));
            ldsm4t(bl[6][0], bl[6][1], bl[7][0], bl[7][1], blbase + bconst[3] + (s << 12));
            #pragma unroll
            for (int t = 0; t < 8; t++)
                mma_f16(d[t], a0, a1, a2, a3, bh[t][0], bh[t][1]);
            #pragma unroll
            for (int t = 0; t < 8; t++)
                mma_f16(d[t], a0, a1, a2, a3, bl[t][0], bl[t][1]);
        }

        // ---- bias + relu + fp16 convert (register-resident h, no residual) ----
        uint32_t hh[8][2];
        #pragma unroll
        for (int t = 0; t < 8; t++) {
            int j = ni * 64 + t * 8 + kp;
            float bx = b1s[j], by = b1s[j + 1];
            float h0 = fmaxf(d[t][0] + bx, 0.f);
            float h1 = fmaxf(d[t][1] + by, 0.f);
            float h2 = fmaxf(d[t][2] + bx, 0.f);
            float h3 = fmaxf(d[t][3] + by, 0.f);
            hh[t][0] = pack2h(h0, h1);
            hh[t][1] = pack2h(h2, h3);
        }

        // ---- layer 2 as mma: o = Hh*(W2h + W2l) ----
        float o[4] = {0.f, 0.f, 0.f, 0.f};
        #pragma unroll
        for (int s2 = 0; s2 < 4; s2++) {
            mma_f16(o, hh[2*s2][0], hh[2*s2][1], hh[2*s2+1][0], hh[2*s2+1][1],
                    w2h[s2][0], w2h[s2][1]);
            mma_f16(o, hh[2*s2][0], hh[2*s2][1], hh[2*s2+1][0], hh[2*s2+1][1],
                    w2l[s2][0], w2l[s2][1]);
        }

        // ---- cross-ni reduction + softmax + dual store ----
        const int row = mi * 16 + cc;
        if (ni == 1) {
            *(float2*)(part + row * 8 + kp)       = make_float2(o[0], o[1]);
            *(float2*)(part + (row + 8) * 8 + kp) = make_float2(o[2], o[3]);
        }
        __syncthreads();
        if (ni == 0) {
            float2 p0 = *(const float2*)(part + row * 8 + kp);
            float2 p1 = *(const float2*)(part + (row + 8) * 8 + kp);
            float bx = b2s[kp], by = b2s[kp + 1];
            float x0 = o[0] + p0.x + bx, x1 = o[1] + p0.y + by;
            float x2 = o[2] + p1.x + bx, x3 = o[3] + p1.y + by;
            float m0 = fmaxf(x0, x1), m1 = fmaxf(x2, x3);
            m0 = fmaxf(m0, __shfl_xor_sync(0xffffffffu, m0, 1));
            m0 = fmaxf(m0, __shfl_xor_sync(0xffffffffu, m0, 2));
            m1 = fmaxf(m1, __shfl_xor_sync(0xffffffffu, m1, 1));
            m1 = fmaxf(m1, __shfl_xor_sync(0xffffffffu, m1, 2));
            float e0 = __expf(x0 - m0), e1 = __expf(x1 - m0);
            float e2 = __expf(x2 - m1), e3 = __expf(x3 - m1);
            float s0 = e0 + e1, s1 = e2 + e3;
            s0 += __shfl_xor_sync(0xffffffffu, s0, 1);
            s0 += __shfl_xor_sync(0xffffffffu, s0, 2);
            s1 += __shfl_xor_sync(0xffffffffu, s1, 1);
            s1 += __shfl_xor_sync(0xffffffffu, s1, 2);
            const int gn0 = node0 + row, gn1 = node0 + row + 8;
            const int q = kp >> 1;
            if (gn0 < NN) {
                float v0 = e0 / s0, v1 = e1 / s0;
                *(float2*)(g_probs + (size_t)gn0 * NC + kp) = make_float2(v0, v1);
                g_probs_h[(size_t)gn0 * 4 + q] = __floats2half2_rn(v0, v1);
            }
            if (gn1 < NN) {
                float v2 = e2 / s1, v3 = e3 / s1;
                *(float2*)(g_probs + (size_t)gn1 * NC + kp) = make_float2(v2, v3);
                g_probs_h[(size_t)gn1 * 4 + q] = __floats2half2_rn(v2, v3);
            }
        }
        __syncthreads();   // protect part + A before next tile
    }
}

// ---------------------------------------------------------------------------
// Stage 2: gather/aggregate. 4 threads/node (class pair q). Loop order
// restructured for memory-level parallelism: per k-chunk i, ALL 5 schemes'
// int4 indices load first, then all 20 half2 gathers issue independently
// (vs 4+16 serialized per scheme before). Gathers hit the 800KB fp16 mirror
// (better L1 residency); self-pred reads the fp32 probs.
// ---------------------------------------------------------------------------
__global__ __launch_bounds__(128)
void aggregate_kernel(const int* __restrict__ nei,
                      const float* __restrict__ attention,
                      const float* __restrict__ alpha,
                      float* __restrict__ out)
{
    const int t = blockIdx.x * blockDim.x + threadIdx.x;
    const int n = t >> 2;
    const int q = t & 3;
    if (n >= NN) return;

    // softmax over 5 scheme-attention logits -> per-scheme weights
    float a[NS];
    #pragma unroll
    for (int s = 0; s < NS; s++) a[s] = attention[n * NS + s];
    float m = a[0];
    #pragma unroll
    for (int s = 1; s < NS; s++) m = fmaxf(m, a[s]);
    float asum = 0.f;
    #pragma unroll
    for (int s = 0; s < NS; s++) { a[s] = __expf(a[s] - m); asum += a[s]; }
    const float inv_asum = 1.f / asum;
    #pragma unroll
    for (int s = 0; s < NS; s++) a[s] *= inv_asum;

    const int4* nb = (const int4*)nei;    // [s][n][4] int4 chunks
    const __half2* ph = g_probs_h;

    float ax = 0.f, ay = 0.f;
    #pragma unroll
    for (int i = 0; i < 4; i++) {
        int4 id[NS];
        #pragma unroll
        for (int s = 0; s < NS; s++)
            id[s] = __ldg(&nb[((size_t)s * NN + n) * 4 + i]);
        #pragma unroll
        for (int s = 0; s < NS; s++) {
            float2 p0 = __half22float2(__ldg(&ph[(size_t)id[s].x * 4 + q]));
            float2 p1 = __half22float2(__ldg(&ph[(size_t)id[s].y * 4 + q]));
            float2 p2 = __half22float2(__ldg(&ph[(size_t)id[s].z * 4 + q]));
            float2 p3 = __half22float2(__ldg(&ph[(size_t)id[s].w * 4 + q]));
            ax = fmaf(a[s], (p0.x + p1.x) + (p2.x + p3.x), ax);
            ay = fmaf(a[s], (p0.y + p1.y) + (p2.y + p3.y), ay);
        }
    }
    ax *= (1.f / (float)NK);
    ay *= (1.f / (float)NK);

    const float gg = 1.f / (1.f + __expf(-alpha[n]));
    const float2 sp = ((const float2*)(g_probs + (size_t)n * NC))[q];
    float2 o;
    o.x = gg * sp.x + (1.f - gg) * ax;
    o.y = gg * sp.y + (1.f - gg) * ay;
    ((float2*)out)[n * 4 + q] = o;
}

// ---------------------------------------------------------------------------
// Launch. Inputs: sc_nei i32[5*50000*16], feats f32[50000*128], W1 f32[128*128],
// b1 f32[128], W2 f32[128*8], b2 f32[8], alpha f32[50000], attention f32[50000*5].
// Output f32[50000*8].
// ---------------------------------------------------------------------------
extern "C" void kernel_launch(void* const* d_in, const int* in_sizes, int n_in,
                              void* d_out, int out_size)
{
    const int*   sc_nei    = (const int*)  d_in[0];
    const float* feats     = (const float*)d_in[1];
    const float* W1        = (const float*)d_in[2];
    const float* b1        = (const float*)d_in[3];
    const float* W2        = (const float*)d_in[4];
    const float* b2        = (const float*)d_in[5];
    const float* alpha     = (const float*)d_in[6];
    const float* attention = (const float*)d_in[7];
    float*       out       = (float*)d_out;

    cudaFuncSetAttribute(mlp_tc_kernel,
                         cudaFuncAttributeMaxDynamicSharedMemorySize,
                         SMEM_TOTAL);

    mlp_tc_kernel<<<GRID1, 256, SMEM_TOTAL>>>(feats, W1, b1, W2, b2);

    const int agg_threads = NN * 4;                 // 200000
    aggregate_kernel<<<(agg_threads + 127) / 128, 128>>>(sc_nei, attention, alpha, out);
}

// round 16
// speedup vs baseline: 1.0566x; 1.0566x over previous
#include <cuda_runtime.h>
#include <cuda_fp16.h>
#include <cstdint>

// Problem constants
#define NN   50000
#define HID  128
#define NC   8
#define NS   5
#define NK   16
#define TM   64                          // nodes per tile
#define NT2  ((NN + TM - 1) / TM)        // 782 tiles
#define GRID1 444                        // persistent CTAs, 3 per SM

// probs scratch: fp32 (self-pred reads) + fp16 mirror (neighbor gathers).
__device__ float   g_probs[NN * NC];       // 1.6MB
__device__ __half2 g_probs_h[NN * 4];      // 800KB

// ---------------------------------------------------------------------------
// SMEM layout (bytes). W1 fp16 image stored [k][n] (.trans-fed, single pass);
// A fp16 image [m][k]. Rows are 256B = 16 chunks of 16B; chunk index
// XOR-swizzled with (row & 7) for conflict-free ldmatrix.
// Total 54.6KB -> 3 CTAs/SM (164KB < 228KB).
// ---------------------------------------------------------------------------
#define OFF_BH   0                        // 128x128 fp16 = 32768
#define OFF_AH   32768                    // 64x128 fp16 = 16384
#define OFF_W2   49152                    // 128x8 f32 = 4096
#define OFF_B1   53248                    // 128 f32
#define OFF_B2   53760                    // 8 f32 (+pad)
#define OFF_PART 53888                    // 64x8 f32 = 2048
#define SMEM_TOTAL 55936

__device__ __forceinline__ uint32_t smem_u32(const void* p) {
    uint32_t a;
    asm("{ .reg .u64 t; cvta.to.shared.u64 t, %1; cvt.u32.u64 %0, t; }" : "=r"(a) : "l"(p));
    return a;
}
__device__ __forceinline__ void ldsm4(uint32_t& r0, uint32_t& r1, uint32_t& r2, uint32_t& r3,
                                      uint32_t addr) {
    asm volatile("ldmatrix.sync.aligned.m8n8.x4.shared.b16 {%0,%1,%2,%3}, [%4];"
                 : "=r"(r0), "=r"(r1), "=r"(r2), "=r"(r3) : "r"(addr));
}
__device__ __forceinline__ void ldsm4t(uint32_t& r0, uint32_t& r1, uint32_t& r2, uint32_t& r3,
                                       uint32_t addr) {
    asm volatile("ldmatrix.sync.aligned.m8n8.x4.trans.shared.b16 {%0,%1,%2,%3}, [%4];"
                 : "=r"(r0), "=r"(r1), "=r"(r2), "=r"(r3) : "r"(addr));
}
__device__ __forceinline__ void mma_f16(float* d,
                                        uint32_t a0, uint32_t a1, uint32_t a2, uint32_t a3,
                                        uint32_t b0, uint32_t b1) {
    asm("mma.sync.aligned.m16n8k16.row.col.f32.f16.f16.f32 "
        "{%0,%1,%2,%3}, {%4,%5,%6,%7}, {%8,%9}, {%0,%1,%2,%3};"
        : "+f"(d[0]), "+f"(d[1]), "+f"(d[2]), "+f"(d[3])
        : "r"(a0), "r"(a1), "r"(a2), "r"(a3), "r"(b0), "r"(b1));
}
__device__ __forceinline__ uint32_t pack2h(float x, float y) {
    __half hx = __float2half_rn(x), hy = __float2half_rn(y);
    return (uint32_t)__half_as_ushort(hx) | ((uint32_t)__half_as_ushort(hy) << 16);
}
// Split (x,y) into packed-fp16 hi pair and lo (residual) pair (layer-2 W2 only).
__device__ __forceinline__ void split2h(float x, float y, uint32_t& hi, uint32_t& lo) {
    __half hx = __float2half_rn(x), hy = __float2half_rn(y);
    __half lx = __float2half_rn(x - __half2float(hx));
    __half ly = __float2half_rn(y - __half2float(hy));
    hi = (uint32_t)__half_as_ushort(hx) | ((uint32_t)__half_as_ushort(hy) << 16);
    lo = (uint32_t)__half_as_ushort(lx) | ((uint32_t)__half_as_ushort(ly) << 16);
}

// ---------------------------------------------------------------------------
// Stage 1: probs = softmax(relu(feats@W1+b1)@W2+b2) via HMMA fp16,
// SINGLE-pass layer 1 (D = Ah*Bh, rounding ~2e-4 norm, under the 1e-3 bar),
// 2-pass layer 2 (cheap). 8 warps: mi = w&3 (16 M-rows), ni = w>>2 (64 N-cols).
// 3 CTAs/SM (24 warps) for latency hiding.
// Epilogue stores probs twice: fp32 (self-pred) + half2 (gather mirror).
// ---------------------------------------------------------------------------
__global__ __launch_bounds__(256, 3)
void mlp_tc_kernel(const float* __restrict__ feats,
                   const float* __restrict__ W1,
                   const float* __restrict__ b1,
                   const float* __restrict__ W2,
                   const float* __restrict__ b2)
{
    extern __shared__ char smem[];
    const uint32_t sb = smem_u32(smem);
    const int tid  = threadIdx.x;
    const int lane = tid & 31;
    const int w    = tid >> 5;
    const int mi   = w & 3;
    const int ni   = w >> 2;

    float* W2s  = (float*)(smem + OFF_W2);
    float* b1s  = (float*)(smem + OFF_B1);
    float* b2s  = (float*)(smem + OFF_B2);
    float* part = (float*)(smem + OFF_PART);

    // ---- prologue: W1 -> Bh ([k][n] fp16, swizzled), W2, biases ----
    {
        const float4* w1v = (const float4*)W1;
        #pragma unroll
        for (int r = 0; r < 16; r++) {
            int idx = tid + 256 * r;           // 0..4095
            int k = idx >> 5, q = idx & 31;    // row k, float4 q
            float4 v = w1v[idx];
            uint32_t off = (uint32_t)k * 256 + ((uint32_t)((q >> 1) ^ (k & 7)) << 4)
                         + ((uint32_t)(q & 1) << 3);
            *(uint2*)(smem + OFF_BH + off) =
                make_uint2(pack2h(v.x, v.y), pack2h(v.z, v.w));
        }
        ((float4*)W2s)[tid] = ((const float4*)W2)[tid];   // 1024 floats
        if (tid < HID) b1s[tid] = b1[tid];
        if (tid < NC)  b2s[tid] = b2[tid];
    }
    __syncthreads();

    // ---- per-warp constants ----
    const int cc = lane >> 2;            // class (mma2 n) / D row group
    const int kp = (lane & 3) * 2;       // col-pair base within 8-wide tiles
    const int g  = lane >> 3;            // ldmatrix address group
    const int lr = lane & 7;
    const int g1 = g & 1, g2 = g >> 1;

    // A ldmatrix lane constants
    const int arow = mi * 16 + lr + g1 * 8;
    const uint32_t a_rowoff = (uint32_t)arow * 256;
    const int asw = arow & 7;
    // B ldmatrix lane constants per ntile-pair pp (k-row swizzle index = lr)
    uint32_t bconst[4];
    #pragma unroll
    for (int pp = 0; pp < 4; pp++)
        bconst[pp] = (uint32_t)(lr + g1 * 8) * 256
                   + ((uint32_t)((ni * 8 + 2 * pp + g2) ^ lr) << 4);

    // W2 fragments (hi/lo fp16) for layer-2 mma, precomputed once
    uint32_t w2h[4][2], w2l[4][2];
    #pragma unroll
    for (int s2 = 0; s2 < 4; s2++) {
        int j0 = ni * 64 + s2 * 16 + kp;
        split2h(W2s[j0 * 8 + cc],       W2s[(j0 + 1) * 8 + cc], w2h[s2][0], w2l[s2][0]);
        split2h(W2s[(j0 + 8) * 8 + cc], W2s[(j0 + 9) * 8 + cc], w2h[s2][1], w2l[s2][1]);
    }

    // ---- persistent tile loop ----
    for (int tile = blockIdx.x; tile < NT2; tile += GRID1) {
        const int node0 = tile * TM;

        // A prep: fp32 -> fp16, swizzled [m][k]
        {
            const float4* fv = (const float4*)feats;
            #pragma unroll
            for (int r = 0; r < 8; r++) {
                int idx = tid + 256 * r;          // 0..2047
                int m = idx >> 5, q = idx & 31;
                int gn = node0 + m;
                float4 v = (gn < NN) ? fv[(size_t)gn * 32 + q]
                                     : make_float4(0.f, 0.f, 0.f, 0.f);
                uint32_t off = (uint32_t)m * 256 + ((uint32_t)((q >> 1) ^ (m & 7)) << 4)
                             + ((uint32_t)(q & 1) << 3);
                *(uint2*)(smem + OFF_AH + off) =
                    make_uint2(pack2h(v.x, v.y), pack2h(v.z, v.w));
            }
        }
        __syncthreads();

        // ---- layer 1: single fp16 pass ----
        float d[8][4];
        #pragma unroll
        for (int t = 0; t < 8; t++) { d[t][0] = d[t][1] = d[t][2] = d[t][3] = 0.f; }

        const uint32_t abase  = sb + OFF_AH + a_rowoff;
        const uint32_t bhbase = sb + OFF_BH;
        #pragma unroll
        for (int s = 0; s < 8; s++) {
            uint32_t a0, a1, a2, a3;
            ldsm4(a0, a1, a2, a3, abase + ((uint32_t)((2 * s + g2) ^ asw) << 4));
            uint32_t bh[8][2];
            ldsm4t(bh[0][0], bh[0][1], bh[1][0], bh[1][1], bhbase + bconst[0] + (s << 12));
            ldsm4t(bh[2][0], bh[2][1], bh[3][0], bh[3][1], bhbase + bconst[1] + (s << 12));
            ldsm4t(bh[4][0], bh[4][1], bh[5][0], bh[5][1], bhbase + bconst[2] + (s << 12));
            ldsm4t(bh[6][0], bh[6][1], bh[7][0], bh[7][1], bhbase + bconst[3] + (s << 12));
            #pragma unroll
            for (int t = 0; t < 8; t++)
                mma_f16(d[t], a0, a1, a2, a3, bh[t][0], bh[t][1]);
        }

        // ---- bias + relu + fp16 convert (register-resident h) ----
        uint32_t hh[8][2];
        #pragma unroll
        for (int t = 0; t < 8; t++) {
            int j = ni * 64 + t * 8 + kp;
            float bx = b1s[j], by = b1s[j + 1];
            float h0 = fmaxf(d[t][0] + bx, 0.f);
            float h1 = fmaxf(d[t][1] + by, 0.f);
            float h2 = fmaxf(d[t][2] + bx, 0.f);
            float h3 = fmaxf(d[t][3] + by, 0.f);
            hh[t][0] = pack2h(h0, h1);
            hh[t][1] = pack2h(h2, h3);
        }

        // ---- layer 2 as mma: o = Hh*(W2h + W2l) ----
        float o[4] = {0.f, 0.f, 0.f, 0.f};
        #pragma unroll
        for (int s2 = 0; s2 < 4; s2++) {
            mma_f16(o, hh[2*s2][0], hh[2*s2][1], hh[2*s2+1][0], hh[2*s2+1][1],
                    w2h[s2][0], w2h[s2][1]);
            mma_f16(o, hh[2*s2][0], hh[2*s2][1], hh[2*s2+1][0], hh[2*s2+1][1],
                    w2l[s2][0], w2l[s2][1]);
        }

        // ---- cross-ni reduction + softmax + dual store ----
        const int row = mi * 16 + cc;
        if (ni == 1) {
            *(float2*)(part + row * 8 + kp)       = make_float2(o[0], o[1]);
            *(float2*)(part + (row + 8) * 8 + kp) = make_float2(o[2], o[3]);
        }
        __syncthreads();
        if (ni == 0) {
            float2 p0 = *(const float2*)(part + row * 8 + kp);
            float2 p1 = *(const float2*)(part + (row + 8) * 8 + kp);
            float bx = b2s[kp], by = b2s[kp + 1];
            float x0 = o[0] + p0.x + bx, x1 = o[1] + p0.y + by;
            float x2 = o[2] + p1.x + bx, x3 = o[3] + p1.y + by;
            float m0 = fmaxf(x0, x1), m1 = fmaxf(x2, x3);
            m0 = fmaxf(m0, __shfl_xor_sync(0xffffffffu, m0, 1));
            m0 = fmaxf(m0, __shfl_xor_sync(0xffffffffu, m0, 2));
            m1 = fmaxf(m1, __shfl_xor_sync(0xffffffffu, m1, 1));
            m1 = fmaxf(m1, __shfl_xor_sync(0xffffffffu, m1, 2));
            float e0 = __expf(x0 - m0), e1 = __expf(x1 - m0);
            float e2 = __expf(x2 - m1), e3 = __expf(x3 - m1);
            float s0 = e0 + e1, s1 = e2 + e3;
            s0 += __shfl_xor_sync(0xffffffffu, s0, 1);
            s0 += __shfl_xor_sync(0xffffffffu, s0, 2);
            s1 += __shfl_xor_sync(0xffffffffu, s1, 1);
            s1 += __shfl_xor_sync(0xffffffffu, s1, 2);
            const int gn0 = node0 + row, gn1 = node0 + row + 8;
            const int q = kp >> 1;
            if (gn0 < NN) {
                float v0 = e0 / s0, v1 = e1 / s0;
                *(float2*)(g_probs + (size_t)gn0 * NC + kp) = make_float2(v0, v1);
                g_probs_h[(size_t)gn0 * 4 + q] = __floats2half2_rn(v0, v1);
            }
            if (gn1 < NN) {
                float v2 = e2 / s1, v3 = e3 / s1;
                *(float2*)(g_probs + (size_t)gn1 * NC + kp) = make_float2(v2, v3);
                g_probs_h[(size_t)gn1 * 4 + q] = __floats2half2_rn(v2, v3);
            }
        }
        __syncthreads();   // protect part + A before next tile
    }
}

// ---------------------------------------------------------------------------
// Stage 2 (unchanged, ~21us, at its L1-wavefront floor): 4 threads/node
// (class pair q); per k-chunk all 5 schemes' int4 indices load first, then
// 20 independent half2 gathers from the fp16 mirror.
// ---------------------------------------------------------------------------
__global__ __launch_bounds__(128)
void aggregate_kernel(const int* __restrict__ nei,
                      const float* __restrict__ attention,
                      const float* __restrict__ alpha,
                      float* __restrict__ out)
{
    const int t = blockIdx.x * blockDim.x + threadIdx.x;
    const int n = t >> 2;
    const int q = t & 3;
    if (n >= NN) return;

    float a[NS];
    #pragma unroll
    for (int s = 0; s < NS; s++) a[s] = attention[n * NS + s];
    float m = a[0];
    #pragma unroll
    for (int s = 1; s < NS; s++) m = fmaxf(m, a[s]);
    float asum = 0.f;
    #pragma unroll
    for (int s = 0; s < NS; s++) { a[s] = __expf(a[s] - m); asum += a[s]; }
    const float inv_asum = 1.f / asum;
    #pragma unroll
    for (int s = 0; s < NS; s++) a[s] *= inv_asum;

    const int4* nb = (const int4*)nei;    // [s][n][4] int4 chunks
    const __half2* ph = g_probs_h;

    float ax = 0.f, ay = 0.f;
    #pragma unroll
    for (int i = 0; i < 4; i++) {
        int4 id[NS];
        #pragma unroll
        for (int s = 0; s < NS; s++)
            id[s] = __ldg(&nb[((size_t)s * NN + n) * 4 + i]);
        #pragma unroll
        for (int s = 0; s < NS; s++) {
            float2 p0 = __half22float2(__ldg(&ph[(size_t)id[s].x * 4 + q]));
            float2 p1 = __half22float2(__ldg(&ph[(size_t)id[s].y * 4 + q]));
            float2 p2 = __half22float2(__ldg(&ph[(size_t)id[s].z * 4 + q]));
            float2 p3 = __half22float2(__ldg(&ph[(size_t)id[s].w * 4 + q]));
            ax = fmaf(a[s], (p0.x + p1.x) + (p2.x + p3.x), ax);
            ay = fmaf(a[s], (p0.y + p1.y) + (p2.y + p3.y), ay);
        }
    }
    ax *= (1.f / (float)NK);
    ay *= (1.f / (float)NK);

    const float gg = 1.f / (1.f + __expf(-alpha[n]));
    const float2 sp = ((const float2*)(g_probs + (size_t)n * NC))[q];
    float2 o;
    o.x = gg * sp.x + (1.f - gg) * ax;
    o.y = gg * sp.y + (1.f - gg) * ay;
    ((float2*)out)[n * 4 + q] = o;
}

// ---------------------------------------------------------------------------
// Launch. Inputs: sc_nei i32[5*50000*16], feats f32[50000*128], W1 f32[128*128],
// b1 f32[128], W2 f32[128*8], b2 f32[8], alpha f32[50000], attention f32[50000*5].
// Output f32[50000*8].
// ---------------------------------------------------------------------------
extern "C" void kernel_launch(void* const* d_in, const int* in_sizes, int n_in,
                              void* d_out, int out_size)
{
    const int*   sc_nei    = (const int*)  d_in[0];
    const float* feats     = (const float*)d_in[1];
    const float* W1        = (const float*)d_in[2];
    const float* b1        = (const float*)d_in[3];
    const float* W2        = (const float*)d_in[4];
    const float* b2        = (const float*)d_in[5];
    const float* alpha     = (const float*)d_in[6];
    const float* attention = (const float*)d_in[7];
    float*       out       = (float*)d_out;

    cudaFuncSetAttribute(mlp_tc_kernel,
                         cudaFuncAttributeMaxDynamicSharedMemorySize,
                         SMEM_TOTAL);

    mlp_tc_kernel<<<GRID1, 256, SMEM_TOTAL>>>(feats, W1, b1, W2, b2);

    const int agg_threads = NN * 4;                 // 200000
    aggregate_kernel<<<(agg_threads + 127) / 128, 128>>>(sc_nei, attention, alpha, out);
}